// round 1
// baseline (speedup 1.0000x reference)
#include <cuda_runtime.h>
#include <math.h>

#define NB   512
#define C0   256
#define M    80
#define PIX  676      // 26*26
#define PPIX 784      // 28*28
#define CHUNK 16

__device__ float g_y [512u*256u*784u];   // deconv output (28x28)
__device__ float g_xp[512u*80u*676u];    // preproc output "x"
__device__ float g_h [512u*80u*676u];    // hidden state
__device__ float g_hg[512u*80u*676u];    // h * g1
__device__ float g_ns[512u*80u*676u];    // ns1

__device__ __forceinline__ float sigm_(float v) { return 1.f / (1.f + expf(-v)); }
__device__ __forceinline__ float sftp_(float v) { return fmaxf(v, 0.f) + log1pf(expf(-fabsf(v))); }

// ---------------------------------------------------------------------------
// Deconv 2x2 / stride 2.  Block: (8 input pixels, n); 256 threads = out ch.
// ---------------------------------------------------------------------------
__global__ __launch_bounds__(256) void k_deconv(const float* __restrict__ x,
                                                const float4* __restrict__ dw4,
                                                const float* __restrict__ db)
{
    __shared__ float xs[8][256];
    const int n = blockIdx.y;
    const int pid0 = blockIdx.x * 8;
    const int tid = threadIdx.x;

    #pragma unroll
    for (int g = 0; g < 8; g++) {
        int pid = pid0 + g;
        xs[g][tid] = (pid < 196) ? x[(n*256 + tid)*196 + pid] : 0.f;
    }
    __syncthreads();

    float acc[8][4];
    #pragma unroll
    for (int g = 0; g < 8; g++)
        #pragma unroll
        for (int k = 0; k < 4; k++) acc[g][k] = 0.f;

    for (int ch = 0; ch < 256; ch++) {
        float4 w = dw4[ch*256 + tid];
        #pragma unroll
        for (int g = 0; g < 8; g++) {
            float xv = xs[g][ch];
            acc[g][0] = fmaf(xv, w.x, acc[g][0]);
            acc[g][1] = fmaf(xv, w.y, acc[g][1]);
            acc[g][2] = fmaf(xv, w.z, acc[g][2]);
            acc[g][3] = fmaf(xv, w.w, acc[g][3]);
        }
    }

    const float b = db[tid];
    #pragma unroll
    for (int g = 0; g < 8; g++) {
        int pid = pid0 + g;
        if (pid < 196) {
            int i = pid / 14, j = pid % 14;
            float* yp = &g_y[(n*256 + tid)*784 + (2*i)*28 + 2*j];
            yp[0]  = acc[g][0] + b;
            yp[1]  = acc[g][1] + b;
            yp[28] = acc[g][2] + b;
            yp[29] = acc[g][3] + b;
        }
    }
}

// ---------------------------------------------------------------------------
// Preproc: 3x3 VALID conv, 256 -> 80, input g_y (28x28), output g_xp (26x26).
// ---------------------------------------------------------------------------
__global__ __launch_bounds__(256, 2) void k_preproc(const float* __restrict__ w,
                                                    const float* __restrict__ bias)
{
    extern __shared__ float sm[];
    float* sIn = sm;
    float* sW  = sm + CHUNK*PPIX;
    const int n = blockIdx.y, mt = blockIdx.x, tid = threadIdx.x;

    int pb[3];
    #pragma unroll
    for (int px = 0; px < 3; px++) {
        int p = tid + px*256; if (p >= PIX) p = 0;
        pb[px] = (p/26)*28 + (p%26);
    }

    float acc[3][8];
    #pragma unroll
    for (int px = 0; px < 3; px++)
        #pragma unroll
        for (int ml = 0; ml < 8; ml++) acc[px][ml] = 0.f;

    for (int cc0 = 0; cc0 < C0; cc0 += CHUNK) {
        __syncthreads();
        for (int idx = tid; idx < CHUNK*PPIX; idx += 256) {
            int c = idx / PPIX, pp = idx - c*PPIX;
            sIn[idx] = g_y[(n*256 + cc0 + c)*784 + pp];
        }
        for (int idx = tid; idx < 8*CHUNK*9; idx += 256) {
            int ml = idx / (CHUNK*9), r = idx - ml*CHUNK*9, c = r/9, t = r - c*9;
            sW[idx] = w[((mt*8 + ml)*C0 + cc0 + c)*9 + t];
        }
        __syncthreads();

        #pragma unroll 1
        for (int c = 0; c < CHUNK; c++) {
            float in9[3][9];
            #pragma unroll
            for (int px = 0; px < 3; px++) {
                const float* s = &sIn[c*PPIX + pb[px]];
                #pragma unroll
                for (int t = 0; t < 9; t++) in9[px][t] = s[(t/3)*28 + (t%3)];
            }
            #pragma unroll
            for (int ml = 0; ml < 8; ml++) {
                float wv[9];
                #pragma unroll
                for (int t = 0; t < 9; t++) wv[t] = sW[ml*CHUNK*9 + c*9 + t];
                #pragma unroll
                for (int px = 0; px < 3; px++)
                    #pragma unroll
                    for (int t = 0; t < 9; t++)
                        acc[px][ml] = fmaf(in9[px][t], wv[t], acc[px][ml]);
            }
        }
    }

    #pragma unroll
    for (int ml = 0; ml < 8; ml++) {
        int m = mt*8 + ml;
        float b = bias[m];
        #pragma unroll
        for (int px = 0; px < 3; px++) {
            int p = tid + px*256;
            if (p < PIX) g_xp[(n*M + m)*PIX + p] = acc[px][ml] + b;
        }
    }
}

// ---------------------------------------------------------------------------
// t=0 shortcut: h = 0, ns1 = softplus(xp)
// ---------------------------------------------------------------------------
__global__ void k_init()
{
    int i = blockIdx.x*blockDim.x + threadIdx.x;
    if (i < NB*M*PIX) {
        g_h[i]  = 0.f;
        g_ns[i] = sftp_(g_xp[i]);
    }
}

// ---------------------------------------------------------------------------
// Gate 1 (1x1): hg = h * sigmoid(u1 . h + b1)
// ---------------------------------------------------------------------------
__global__ __launch_bounds__(256, 2) void k_gate1(const float* __restrict__ u1w,
                                                  const float* __restrict__ u1b)
{
    __shared__ float sw[M*M];
    __shared__ float sb[M];
    const int n = blockIdx.y, tid = threadIdx.x;

    for (int idx = tid; idx < M*M; idx += 256) sw[idx] = u1w[idx];
    if (tid < M) sb[tid] = u1b[tid];
    __syncthreads();

    const int p = blockIdx.x*256 + tid;
    if (p >= PIX) return;

    float hl[M];
    const float* hp = &g_h[n*M*PIX + p];
    #pragma unroll
    for (int c = 0; c < M; c++) hl[c] = hp[c*PIX];

    float* op = &g_hg[n*M*PIX + p];
    const float4* sw4 = (const float4*)sw;
    for (int m = 0; m < M; m++) {
        float acc = sb[m];
        #pragma unroll
        for (int c4 = 0; c4 < M/4; c4++) {
            float4 w = sw4[m*(M/4) + c4];
            acc = fmaf(hl[c4*4+0], w.x, acc);
            acc = fmaf(hl[c4*4+1], w.y, acc);
            acc = fmaf(hl[c4*4+2], w.z, acc);
            acc = fmaf(hl[c4*4+3], w.w, acc);
        }
        op[m*PIX] = hp[m*PIX] * sigm_(acc);
    }
}

// ---------------------------------------------------------------------------
// Conv inh (3x3 SAME on g_hg) + ns1 = softplus(xp - c1*(alpha*h + mu))
// ---------------------------------------------------------------------------
__global__ __launch_bounds__(256, 2) void k_conv_inh(const float* __restrict__ w,
                                                     const float* __restrict__ alpha,
                                                     const float* __restrict__ mu)
{
    extern __shared__ float sm[];
    float* sIn = sm;
    float* sW  = sm + CHUNK*PPIX;
    const int n = blockIdx.y, mt = blockIdx.x, tid = threadIdx.x;

    int pb[3];
    #pragma unroll
    for (int px = 0; px < 3; px++) {
        int p = tid + px*256; if (p >= PIX) p = 0;
        pb[px] = (p/26)*28 + (p%26);
    }

    float acc[3][8];
    #pragma unroll
    for (int px = 0; px < 3; px++)
        #pragma unroll
        for (int ml = 0; ml < 8; ml++) acc[px][ml] = 0.f;

    for (int cc0 = 0; cc0 < M; cc0 += CHUNK) {
        __syncthreads();
        for (int idx = tid; idx < CHUNK*PPIX; idx += 256) {
            int c = idx / PPIX, pp = idx - c*PPIX, y = pp/28, xx = pp - y*28;
            float v = 0.f;
            if (y >= 1 && y <= 26 && xx >= 1 && xx <= 26)
                v = g_hg[(n*M + cc0 + c)*PIX + (y-1)*26 + (xx-1)];
            sIn[idx] = v;
        }
        for (int idx = tid; idx < 8*CHUNK*9; idx += 256) {
            int ml = idx / (CHUNK*9), r = idx - ml*CHUNK*9, c = r/9, t = r - c*9;
            sW[idx] = w[((mt*8 + ml)*M + cc0 + c)*9 + t];
        }
        __syncthreads();

        #pragma unroll 1
        for (int c = 0; c < CHUNK; c++) {
            float in9[3][9];
            #pragma unroll
            for (int px = 0; px < 3; px++) {
                const float* s = &sIn[c*PPIX + pb[px]];
                #pragma unroll
                for (int t = 0; t < 9; t++) in9[px][t] = s[(t/3)*28 + (t%3)];
            }
            #pragma unroll
            for (int ml = 0; ml < 8; ml++) {
                float wv[9];
                #pragma unroll
                for (int t = 0; t < 9; t++) wv[t] = sW[ml*CHUNK*9 + c*9 + t];
                #pragma unroll
                for (int px = 0; px < 3; px++)
                    #pragma unroll
                    for (int t = 0; t < 9; t++)
                        acc[px][ml] = fmaf(in9[px][t], wv[t], acc[px][ml]);
            }
        }
    }

    #pragma unroll
    for (int ml = 0; ml < 8; ml++) {
        int m = mt*8 + ml;
        float a  = alpha[m];
        float mm = mu[m];
        #pragma unroll
        for (int px = 0; px < 3; px++) {
            int p = tid + px*256;
            if (p < PIX) {
                int idx = (n*M + m)*PIX + p;
                float hv = g_h[idx];
                float xv = g_xp[idx];
                g_ns[idx] = sftp_(xv - acc[px][ml]*(a*hv + mm));
            }
        }
    }
}

// ---------------------------------------------------------------------------
// Conv exc (3x3 SAME on g_ns) + fused u2 gate + GRU blend.
// WRITE_OUT: 0 -> write g_h (intermediate steps), 1 -> write `out` (last step)
// ---------------------------------------------------------------------------
template<int WRITE_OUT>
__global__ __launch_bounds__(256, 2) void k_conv_exc(const float* __restrict__ w,
                                                     const float* __restrict__ u2w,
                                                     const float* __restrict__ u2b,
                                                     float* __restrict__ out)
{
    extern __shared__ float sm[];
    float* sIn = sm;
    float* sW  = sm + CHUNK*PPIX;
    float* sU2 = sW + 8*CHUNK*9;
    const int n = blockIdx.y, mt = blockIdx.x, tid = threadIdx.x;

    int pb[3];
    #pragma unroll
    for (int px = 0; px < 3; px++) {
        int p = tid + px*256; if (p >= PIX) p = 0;
        pb[px] = (p/26)*28 + (p%26);
    }

    float acc[3][8], g2a[3][8];
    #pragma unroll
    for (int px = 0; px < 3; px++)
        #pragma unroll
        for (int ml = 0; ml < 8; ml++) { acc[px][ml] = 0.f; g2a[px][ml] = 0.f; }

    for (int cc0 = 0; cc0 < M; cc0 += CHUNK) {
        __syncthreads();
        for (int idx = tid; idx < CHUNK*PPIX; idx += 256) {
            int c = idx / PPIX, pp = idx - c*PPIX, y = pp/28, xx = pp - y*28;
            float v = 0.f;
            if (y >= 1 && y <= 26 && xx >= 1 && xx <= 26)
                v = g_ns[(n*M + cc0 + c)*PIX + (y-1)*26 + (xx-1)];
            sIn[idx] = v;
        }
        for (int idx = tid; idx < 8*CHUNK*9; idx += 256) {
            int ml = idx / (CHUNK*9), r = idx - ml*CHUNK*9, c = r/9, t = r - c*9;
            sW[idx] = w[((mt*8 + ml)*M + cc0 + c)*9 + t];
        }
        if (tid < 8*CHUNK)
            sU2[tid] = u2w[(mt*8 + tid/CHUNK)*M + cc0 + (tid % CHUNK)];
        __syncthreads();

        #pragma unroll 1
        for (int c = 0; c < CHUNK; c++) {
            float in9[3][9];
            #pragma unroll
            for (int px = 0; px < 3; px++) {
                const float* s = &sIn[c*PPIX + pb[px]];
                #pragma unroll
                for (int t = 0; t < 9; t++) in9[px][t] = s[(t/3)*28 + (t%3)];
            }
            #pragma unroll
            for (int ml = 0; ml < 8; ml++) {
                float wv[9];
                #pragma unroll
                for (int t = 0; t < 9; t++) wv[t] = sW[ml*CHUNK*9 + c*9 + t];
                float uw = sU2[ml*CHUNK + c];
                #pragma unroll
                for (int px = 0; px < 3; px++) {
                    #pragma unroll
                    for (int t = 0; t < 9; t++)
                        acc[px][ml] = fmaf(in9[px][t], wv[t], acc[px][ml]);
                    g2a[px][ml] = fmaf(in9[px][4], uw, g2a[px][ml]);  // center tap = u2 1x1
                }
            }
        }
    }

    #pragma unroll
    for (int ml = 0; ml < 8; ml++) {
        int m = mt*8 + ml;
        float b = u2b[m];
        #pragma unroll
        for (int px = 0; px < 3; px++) {
            int p = tid + px*256;
            if (p < PIX) {
                int idx = (n*M + m)*PIX + p;
                float g2 = sigm_(g2a[px][ml] + b);
                float h2 = sftp_(acc[px][ml]);
                float hv = g_h[idx];
                float hn = (1.f - g2)*hv + g2*h2;
                if (WRITE_OUT) out[idx] = hn;
                else           g_h[idx] = hn;
            }
        }
    }
}

// ---------------------------------------------------------------------------
extern "C" void kernel_launch(void* const* d_in, const int* in_sizes, int n_in,
                              void* d_out, int out_size)
{
    const float* x        = (const float*)d_in[0];
    const float* deconv_w = (const float*)d_in[1];
    const float* deconv_b = (const float*)d_in[2];
    const float* pre_w    = (const float*)d_in[3];
    const float* pre_b    = (const float*)d_in[4];
    const float* u1_w     = (const float*)d_in[5];
    const float* u1_b     = (const float*)d_in[6];
    const float* u2_w     = (const float*)d_in[7];
    const float* u2_b     = (const float*)d_in[8];
    const float* w_inh    = (const float*)d_in[9];
    const float* w_exc    = (const float*)d_in[10];
    const float* alpha    = (const float*)d_in[11];
    const float* mu       = (const float*)d_in[12];
    float* out = (float*)d_out;

    const int smemB = (CHUNK*PPIX + 8*CHUNK*9) * 4;          // 54,784 B
    const int smemD = (CHUNK*PPIX + 8*CHUNK*9 + 8*CHUNK)*4;  // 55,296 B
    cudaFuncSetAttribute(k_preproc,      cudaFuncAttributeMaxDynamicSharedMemorySize, smemB);
    cudaFuncSetAttribute(k_conv_inh,     cudaFuncAttributeMaxDynamicSharedMemorySize, smemB);
    cudaFuncSetAttribute(k_conv_exc<0>,  cudaFuncAttributeMaxDynamicSharedMemorySize, smemD);
    cudaFuncSetAttribute(k_conv_exc<1>,  cudaFuncAttributeMaxDynamicSharedMemorySize, smemD);

    // Feedforward: deconv + preproc
    k_deconv <<<dim3(25, NB), 256>>>(x, (const float4*)deconv_w, deconv_b);
    k_preproc<<<dim3(10, NB), 256, smemB>>>(pre_w, pre_b);

    // t = 0 (h == 0 -> hg == 0 -> c1 == 0 -> ns1 = softplus(xp))
    k_init<<<(NB*M*PIX + 255)/256, 256>>>();
    k_conv_exc<0><<<dim3(10, NB), 256, smemD>>>(w_exc, u2_w, u2_b, nullptr);

    // t = 1 .. 9
    for (int t = 1; t < 10; t++) {
        k_gate1   <<<dim3(3,  NB), 256>>>(u1_w, u1_b);
        k_conv_inh<<<dim3(10, NB), 256, smemB>>>(w_inh, alpha, mu);
        if (t < 9)
            k_conv_exc<0><<<dim3(10, NB), 256, smemD>>>(w_exc, u2_w, u2_b, nullptr);
        else
            k_conv_exc<1><<<dim3(10, NB), 256, smemD>>>(w_exc, u2_w, u2_b, out);
    }
}